// round 1
// baseline (speedup 1.0000x reference)
#include <cuda_runtime.h>

#define BATCH 2
#define NPTS 4096
#define NQ    16384
#define AGG_K 451
#define AGG_LD 452

// ---------------- scratch (device globals; no allocation allowed) ----------------
__device__ float g_feat[BATCH * NPTS * 448];           // point-major features [b][n][448]
__device__ float g_pmax[BATCH * 16 * 256];             // partial maxes
__device__ float g_c1[BATCH * 256];                    // folded global-feat bias for r1
__device__ float g_agg[(size_t)BATCH * NQ * AGG_LD];   // agg rows [b][q][451(+1 pad)]
__device__ float g_r1t[AGG_K * 256];                   // transposed r1 (first 451 cols)
__device__ float g_r2t[256 * 128];
__device__ float g_r3t[128 * 64];

// ---------------- f32x2 packed helpers (sm_103a FFMA2 path) ----------------
__device__ __forceinline__ unsigned long long pk2(float x) {
    unsigned long long r;
    asm("mov.b64 %0, {%1, %1};" : "=l"(r) : "f"(x));
    return r;
}
__device__ __forceinline__ void fma2(unsigned long long& acc, unsigned long long a,
                                     unsigned long long b) {
    asm("fma.rn.f32x2 %0, %1, %2, %0;" : "+l"(acc) : "l"(a), "l"(b));
}
__device__ __forceinline__ void upk2(unsigned long long v, float& lo, float& hi) {
    asm("mov.b64 {%0, %1}, %2;" : "=f"(lo), "=f"(hi) : "l"(v));
}

// ---------------- prep: transpose regressor weights ----------------
__global__ void prep_kernel(const float* __restrict__ r1, const float* __restrict__ r2,
                            const float* __restrict__ r3) {
    int stride = gridDim.x * blockDim.x;
    int tid = blockIdx.x * blockDim.x + threadIdx.x;
    for (int idx = tid; idx < AGG_K * 256; idx += stride) {
        int oc = idx & 255, k = idx >> 8;
        g_r1t[idx] = r1[oc * 707 + k];
    }
    for (int idx = tid; idx < 256 * 128; idx += stride) {
        int oc = idx & 127, k = idx >> 7;
        g_r2t[idx] = r2[oc * 256 + k];
    }
    for (int idx = tid; idx < 128 * 64; idx += stride) {
        int oc = idx & 63, k = idx >> 6;
        g_r3t[idx] = r3[oc * 128 + k];
    }
}

// ---------------- feature extractor: fused 3-layer 1x1-conv MLP ----------------
// grid = BATCH * (NPTS/32) blocks, 256 threads. Writes point-major g_feat.
__global__ void feat_kernel(const float* __restrict__ opts,
                            const float* __restrict__ w1, const float* __restrict__ b1,
                            const float* __restrict__ w2, const float* __restrict__ b2,
                            const float* __restrict__ w3, const float* __restrict__ b3) {
    extern __shared__ float sm[];
    float* w2t = sm;             // 64 *129 = 8256
    float* w3t = w2t + 8256;     // 128*257 = 32896
    float* f1s = w3t + 32896;    // 64 *33  = 2112
    float* f2s = f1s + 2112;     // 128*33  = 4224
    float* pts = f2s + 4224;     // 96
    int t = threadIdx.x;
    int bb = blockIdx.x >> 7;
    int base = (blockIdx.x & 127) * 32;

    for (int i = t; i < 128 * 64; i += 256) { int oc = i >> 6, k = i & 63; w2t[k * 129 + oc] = w2[i]; }
    for (int i = t; i < 256 * 128; i += 256) { int oc = i >> 7, k = i & 127; w3t[k * 257 + oc] = w3[i]; }
    for (int i = t; i < 96; i += 256) {
        int d = i >> 5, j = i & 31;
        pts[i] = opts[bb * 3 * NPTS + d * NPTS + base + j];
    }
    __syncthreads();

    // stage 1: 3 -> 64
    {
        int oc = t & 63, jg = t >> 6;
        float wx = w1[oc * 3], wy = w1[oc * 3 + 1], wz = w1[oc * 3 + 2], bia = b1[oc];
        #pragma unroll
        for (int j = jg * 8; j < jg * 8 + 8; j++) {
            float v = fmaf(wx, pts[j], fmaf(wy, pts[32 + j], fmaf(wz, pts[64 + j], bia)));
            v = fmaxf(v, 0.f);
            f1s[oc * 33 + j] = v;
            g_feat[(bb * NPTS + base + j) * 448 + oc] = v;
        }
    }
    __syncthreads();

    // stage 2: 64 -> 128
    {
        int oc = t & 127, half = t >> 7;
        float acc[16];
        float bia = b2[oc];
        #pragma unroll
        for (int i = 0; i < 16; i++) acc[i] = bia;
        for (int k = 0; k < 64; k++) {
            float w = w2t[k * 129 + oc];
            const float* f = &f1s[k * 33 + half * 16];
            #pragma unroll
            for (int i = 0; i < 16; i++) acc[i] = fmaf(w, f[i], acc[i]);
        }
        for (int i = 0; i < 16; i++) {
            float v = fmaxf(acc[i], 0.f);
            int j = half * 16 + i;
            f2s[oc * 33 + j] = v;
            g_feat[(bb * NPTS + base + j) * 448 + 64 + oc] = v;
        }
    }
    __syncthreads();

    // stage 3: 128 -> 256
    {
        int oc = t;
        float acc[32];
        float bia = b3[oc];
        #pragma unroll
        for (int i = 0; i < 32; i++) acc[i] = bia;
        for (int k = 0; k < 128; k++) {
            float w = w3t[k * 257 + oc];
            const float* f = &f2s[k * 33];
            #pragma unroll
            for (int j = 0; j < 32; j++) acc[j] = fmaf(w, f[j], acc[j]);
        }
        for (int j = 0; j < 32; j++)
            g_feat[(bb * NPTS + base + j) * 448 + 192 + oc] = fmaxf(acc[j], 0.f);
    }
}

// ---------------- partial max over points of f3 ----------------
__global__ void pmax_kernel() {
    int t = threadIdx.x;
    int bb = blockIdx.x >> 4, ch = blockIdx.x & 15;
    float m = -3.4e38f;
    int p0 = ch * 256;
    for (int p = p0; p < p0 + 256; p++)
        m = fmaxf(m, g_feat[(bb * NPTS + p) * 448 + 192 + t]);
    g_pmax[(bb * 16 + ch) * 256 + t] = m;
}

// ---------------- finish max + fold global feats into r1 bias ----------------
__global__ void c1_kernel(const float* __restrict__ r1, const float* __restrict__ rb1) {
    __shared__ float fms[256];
    int t = threadIdx.x, bb = blockIdx.x;
    float m = -3.4e38f;
    for (int ch = 0; ch < 16; ch++) m = fmaxf(m, g_pmax[(bb * 16 + ch) * 256 + t]);
    fms[t] = m;
    __syncthreads();
    float s = rb1[t];
    for (int c = 0; c < 256; c++) s = fmaf(r1[t * 707 + 451 + c], fms[c], s);
    g_c1[bb * 256 + t] = s;
}

// ---------------- KNN(3) + inverse-distance interpolation ----------------
// warp per query; originals in smem. grid = BATCH * (NQ/8).
__global__ void knn_kernel(const float* __restrict__ opts, const float* __restrict__ qpts) {
    __shared__ float spt[3 * NPTS];  // sx | sy | sz
    int t = threadIdx.x;
    int bb = blockIdx.x >> 11, tile = blockIdx.x & 2047;
    for (int i = t; i < NPTS; i += 256) {
        spt[i]            = opts[bb * 3 * NPTS + i];
        spt[NPTS + i]     = opts[bb * 3 * NPTS + NPTS + i];
        spt[2 * NPTS + i] = opts[bb * 3 * NPTS + 2 * NPTS + i];
    }
    __syncthreads();
    const float* sx = spt;
    const float* sy = spt + NPTS;
    const float* sz = spt + 2 * NPTS;

    int warp = t >> 5, lane = t & 31;
    int q = tile * 8 + warp;
    float qx = qpts[bb * 3 * NQ + q];
    float qy = qpts[bb * 3 * NQ + NQ + q];
    float qz = qpts[bb * 3 * NQ + 2 * NQ + q];

    float bd0 = 3.4e38f, bd1 = 3.4e38f, bd2 = 3.4e38f;
    int bi0 = 0, bi1 = 0, bi2 = 0;
    for (int p = lane; p < NPTS; p += 32) {
        float dx = qx - sx[p], dy = qy - sy[p], dz = qz - sz[p];
        float dd = fmaf(dx, dx, fmaf(dy, dy, dz * dz));
        if (dd < bd2) {
            if (dd < bd1) {
                bd2 = bd1; bi2 = bi1;
                if (dd < bd0) { bd1 = bd0; bi1 = bi0; bd0 = dd; bi0 = p; }
                else          { bd1 = dd; bi1 = p; }
            } else { bd2 = dd; bi2 = p; }
        }
    }

    // warp merge of per-lane top-3 into warp top-3 (membership only; order irrelevant)
    float bd[3] = {bd0, bd1, bd2};
    int bi[3] = {bi0, bi1, bi2};
    int j = 0;
    int sel[3];
    for (int r = 0; r < 3; r++) {
        float cv = (j < 3) ? bd[j] : 3.4e38f;
        int ci = (j < 3) ? bi[j] : 0;
        float rv = cv; int rl = lane;
        for (int off = 16; off; off >>= 1) {
            float ov = __shfl_down_sync(0xffffffffu, rv, off);
            int ol = __shfl_down_sync(0xffffffffu, rl, off);
            if (ov < rv) { rv = ov; rl = ol; }
        }
        int wl = __shfl_sync(0xffffffffu, rl, 0);
        sel[r] = __shfl_sync(0xffffffffu, ci, wl);
        if (lane == wl) j++;
    }

    float wk[3], wsum = 0.f;
    #pragma unroll
    for (int r = 0; r < 3; r++) {
        int p = sel[r];
        float dx = qx - sx[p], dy = qy - sy[p], dz = qz - sz[p];
        float dist = sqrtf(dx * dx + dy * dy + dz * dz);
        wk[r] = 1.f / (dist + 1e-8f);
        wsum += wk[r];
    }
    float inv = 1.f / wsum;
    wk[0] *= inv; wk[1] *= inv; wk[2] *= inv;

    size_t rowbase = (size_t)(bb * NQ + q) * AGG_LD;
    if (lane == 0) { g_agg[rowbase] = qx; g_agg[rowbase + 1] = qy; g_agg[rowbase + 2] = qz; }
    const float* F0 = g_feat + (size_t)(bb * NPTS + sel[0]) * 448;
    const float* F1 = g_feat + (size_t)(bb * NPTS + sel[1]) * 448;
    const float* F2 = g_feat + (size_t)(bb * NPTS + sel[2]) * 448;
    for (int c = lane; c < 448; c += 32)
        g_agg[rowbase + 3 + c] = wk[0] * F0[c] + wk[1] * F1[c] + wk[2] * F2[c];
}

// ---------------- regressor: 451->256->128->64->1 over 32 queries/block ----------------
__global__ void reg_kernel(const float* __restrict__ rb2, const float* __restrict__ rb3,
                           const float* __restrict__ r4, const float* __restrict__ rb4,
                           float* __restrict__ out) {
    extern __shared__ float sm[];
    float* aggs = sm;            // 451*34 = 15334 words
    float* h1s  = sm + 15334;    // 256*34 = 8704 words
    float* h2s  = sm;            // reuses aggs region: 128*34 = 4352
    float* h3s  = sm + 4352;     // 64*34 = 2176 (inside dead aggs region)
    int t = threadIdx.x;
    int bb = blockIdx.x >> 9, tile = blockIdx.x & 511;
    int qbase = tile * 32;
    size_t gbase = (size_t)(bb * NQ + qbase) * AGG_LD;

    for (int i = t; i < 32 * AGG_K; i += 256) {
        int ql = i / AGG_K, k = i - ql * AGG_K;
        aggs[k * 34 + ql] = g_agg[gbase + (size_t)ql * AGG_LD + k];
    }
    __syncthreads();

    // stage 1: 451 -> 256 (bias includes folded global-feat term)
    {
        int oc = t;
        unsigned long long acc[16];
        unsigned long long cinit = pk2(g_c1[bb * 256 + oc]);
        #pragma unroll
        for (int i = 0; i < 16; i++) acc[i] = cinit;
        for (int k = 0; k < AGG_K; k++) {
            unsigned long long w = pk2(g_r1t[k * 256 + oc]);
            const unsigned long long* ap = (const unsigned long long*)(aggs + k * 34);
            #pragma unroll
            for (int i = 0; i < 16; i++) fma2(acc[i], w, ap[i]);
        }
        #pragma unroll
        for (int i = 0; i < 16; i++) {
            float lo, hi;
            upk2(acc[i], lo, hi);
            h1s[oc * 34 + 2 * i]     = fmaxf(lo, 0.f);
            h1s[oc * 34 + 2 * i + 1] = fmaxf(hi, 0.f);
        }
    }
    __syncthreads();

    // stage 2: 256 -> 128 (writes over dead aggs region)
    {
        int oc = t & 127, half = t >> 7;
        unsigned long long acc[8];
        unsigned long long binit = pk2(rb2[oc]);
        #pragma unroll
        for (int i = 0; i < 8; i++) acc[i] = binit;
        for (int k = 0; k < 256; k++) {
            unsigned long long w = pk2(g_r2t[k * 128 + oc]);
            const unsigned long long* ap = (const unsigned long long*)(h1s + k * 34) + half * 8;
            #pragma unroll
            for (int i = 0; i < 8; i++) fma2(acc[i], w, ap[i]);
        }
        #pragma unroll
        for (int i = 0; i < 8; i++) {
            float lo, hi;
            upk2(acc[i], lo, hi);
            int qp = half * 8 + i;
            h2s[oc * 34 + 2 * qp]     = fmaxf(lo, 0.f);
            h2s[oc * 34 + 2 * qp + 1] = fmaxf(hi, 0.f);
        }
    }
    __syncthreads();

    // stage 3: 128 -> 64
    {
        int oc = t & 63, qr = t >> 6;
        unsigned long long acc[4];
        unsigned long long binit = pk2(rb3[oc]);
        #pragma unroll
        for (int i = 0; i < 4; i++) acc[i] = binit;
        for (int k = 0; k < 128; k++) {
            unsigned long long w = pk2(g_r3t[k * 64 + oc]);
            const unsigned long long* ap = (const unsigned long long*)(h2s + k * 34) + qr * 4;
            #pragma unroll
            for (int i = 0; i < 4; i++) fma2(acc[i], w, ap[i]);
        }
        #pragma unroll
        for (int i = 0; i < 4; i++) {
            float lo, hi;
            upk2(acc[i], lo, hi);
            int qp = qr * 4 + i;
            h3s[oc * 34 + 2 * qp]     = fmaxf(lo, 0.f);
            h3s[oc * 34 + 2 * qp + 1] = fmaxf(hi, 0.f);
        }
    }
    __syncthreads();

    // stage 4: 64 -> 1
    {
        int warp = t >> 5, lane = t & 31;
        int qloc = warp * 4 + (lane >> 3);
        int c0 = lane & 7;
        float p = 0.f;
        #pragma unroll
        for (int jj = 0; jj < 8; jj++) {
            int c = c0 + jj * 8;
            p = fmaf(r4[c], h3s[c * 34 + qloc], p);
        }
        p += __shfl_xor_sync(0xffffffffu, p, 1);
        p += __shfl_xor_sync(0xffffffffu, p, 2);
        p += __shfl_xor_sync(0xffffffffu, p, 4);
        if ((lane & 7) == 0) out[bb * NQ + qbase + qloc] = p + rb4[0];
    }
}

// ---------------- launch ----------------
extern "C" void kernel_launch(void* const* d_in, const int* in_sizes, int n_in,
                              void* d_out, int out_size) {
    const float* opts = (const float*)d_in[0];
    const float* qpts = (const float*)d_in[1];
    const float* w1 = (const float*)d_in[2];
    const float* b1 = (const float*)d_in[3];
    const float* w2 = (const float*)d_in[4];
    const float* b2 = (const float*)d_in[5];
    const float* w3 = (const float*)d_in[6];
    const float* b3 = (const float*)d_in[7];
    const float* r1 = (const float*)d_in[8];
    const float* rb1 = (const float*)d_in[9];
    const float* r3 = (const float*)d_in[12];
    const float* rb3 = (const float*)d_in[13];
    const float* r2 = (const float*)d_in[10];
    const float* rb2 = (const float*)d_in[11];
    const float* r4 = (const float*)d_in[14];
    const float* rb4 = (const float*)d_in[15];
    float* out = (float*)d_out;

    cudaFuncSetAttribute(feat_kernel, cudaFuncAttributeMaxDynamicSharedMemorySize, 190336);
    cudaFuncSetAttribute(reg_kernel, cudaFuncAttributeMaxDynamicSharedMemorySize, 96152);

    prep_kernel<<<64, 256>>>(r1, r2, r3);
    feat_kernel<<<BATCH * (NPTS / 32), 256, 190336>>>(opts, w1, b1, w2, b2, w3, b3);
    pmax_kernel<<<BATCH * 16, 256>>>();
    c1_kernel<<<BATCH, 256>>>(r1, rb1);
    knn_kernel<<<BATCH * (NQ / 8), 256>>>(opts, qpts);
    reg_kernel<<<BATCH * (NQ / 32), 256, 96152>>>(rb2, rb3, r4, rb4, out);
}